// round 9
// baseline (speedup 1.0000x reference)
#include <cuda_runtime.h>
#include <cstddef>

// HealEncoding: out[b, f*NLVL + l] = sum_{n<4} params[l, neigh_pix[l,n,b], f] * neigh_weight[l,n,b]
// params: (8,196608,8) f32; neigh_pix: (8,4,1M) i32; neigh_weight: (8,4,1M) f32; out: (1M,64) f32

#define NLVL  8
#define NPIX  196608
#define BATCH 1000000
#define BBLK  64          // two 32-element passes per block (amortizes smem table)

// Block (32,8): warp == one level. Pair-cooperative gather (lanes 2j,2j+1 split
// the 32B feature row; h = lane&1 -> 16B half). Runtime == total l1tex
// wavefronts (measured 1.0 wf/cyc). vs R8 (137.8us): lvl1+lvl2 tables (7.7KB)
// cached in SMEM per block -> their gathers move from LDG (9 / 13.7 line-
// wavefronts per instr) to LDS.128 (~5.6 phases). Non-persistent: table load
// (60 wf) amortized over 64 elements. lvl0 stays LDG (3 wf/instr, cheaper).
__global__ void __launch_bounds__(256, 8)
heal_encoding_kernel(const float* __restrict__ params,
                     const int*   __restrict__ neigh_pix,
                     const float* __restrict__ neigh_weight,
                     float*       __restrict__ out)
{
    __shared__ float4 s_tab[480];  // lvl1 (48 pix) at [0,96), lvl2 (192 pix) at [96,480)
    __shared__ float  s[64 * 33];  // staging; addr = c*33 + (c>>5) + j2, conflict-free

    const int lane = threadIdx.x;
    const int lvl  = threadIdx.y;          // warp == level
    const int j    = lane >> 1;            // pixel-slot within warp [0,16)
    const int h    = lane & 1;             // 16B half of the 32B feature row
    const int tid  = lvl * 32 + lane;

    // Cooperative table load: lvl1+lvl2 param rows, coalesced float4.
    {
        const float4* __restrict__ g4 = reinterpret_cast<const float4*>(params);
        if (tid < 96) s_tab[tid] = __ldg(&g4[1 * (NPIX * 2) + tid]);
#pragma unroll
        for (int i = 0; i < 2; i++) {
            const int v = i * 256 + tid;
            if (v < 384) s_tab[96 + v] = __ldg(&g4[2 * (NPIX * 2) + v]);
        }
    }
    __syncthreads();

    const bool use_lds  = (lvl == 1) | (lvl == 2);
    const int  tab_off  = (lvl == 1) ? 0 : 96;
    const float4* __restrict__ p4 =
        reinterpret_cast<const float4*>(params) + lvl * (NPIX * 2);

#pragma unroll
    for (int t2 = 0; t2 < 2; t2++) {
        const int b0 = blockIdx.x * BBLK + t2 * 32;

        // Vectorized idx/weight loads: int2/float2 covering elements (2j, 2j+1).
        int2   pix2[4];
        float2 w2[4];
#pragma unroll
        for (int n = 0; n < 4; n++) {
            const int off = (lvl * 4 + n) * BATCH + b0;   // fits int32
            pix2[n] = __ldg(reinterpret_cast<const int2*>(neigh_pix + off) + j);
            w2[n]   = __ldg(reinterpret_cast<const float2*>(neigh_weight + off) + j);
        }

#pragma unroll
        for (int s2 = 0; s2 < 2; s2++) {
            float4 a = make_float4(0.f, 0.f, 0.f, 0.f);

#pragma unroll
            for (int np = 0; np < 2; np++) {
                const int pa = (s2 == 0) ? pix2[2*np+0].x : pix2[2*np+0].y;
                const int pb = (s2 == 0) ? pix2[2*np+1].x : pix2[2*np+1].y;
                float4 g0, g1;
                if (use_lds) {                 // warp-uniform branch
                    g0 = s_tab[tab_off + pa * 2 + h];
                    g1 = s_tab[tab_off + pb * 2 + h];
                } else {
                    g0 = __ldg(&p4[pa * 2 + h]);
                    g1 = __ldg(&p4[pb * 2 + h]);
                }
                const float wa = (s2 == 0) ? w2[2*np+0].x : w2[2*np+0].y;
                const float wb = (s2 == 0) ? w2[2*np+1].x : w2[2*np+1].y;
                a.x = fmaf(wa, g0.x, a.x);  a.x = fmaf(wb, g1.x, a.x);
                a.y = fmaf(wa, g0.y, a.y);  a.y = fmaf(wb, g1.y, a.y);
                a.z = fmaf(wa, g0.z, a.z);  a.z = fmaf(wb, g1.z, a.z);
                a.w = fmaf(wa, g0.w, a.w);  a.w = fmaf(wb, g1.w, a.w);
            }

            // Stage element j2 = 2j+s2; out column c = (4h+k)*8 + lvl.
            // Store bank = const + 2j + h = const + lane: conflict-free.
            const int j2 = 2 * j + s2;
#pragma unroll
            for (int k = 0; k < 4; k++) {
                const int c = (h * 4 + k) * NLVL + lvl;
                const float v = (k == 0) ? a.x : (k == 1) ? a.y : (k == 2) ? a.z : a.w;
                s[c * 33 + (c >> 5) + j2] = v;
            }
        }

        __syncthreads();

        // Coalesced write-out: 32 b x 64 cols = 2048 floats, 8 iters.
        // Read bank = (c + bl + const) % 32 distinct across warp: conflict-free.
        float* __restrict__ outp = out + (size_t)b0 * 64;
#pragma unroll
        for (int i = 0; i < 8; i++) {
            const int e  = i * 256 + tid;
            const int bl = e >> 6;
            const int c  = e & 63;
            outp[e] = s[c * 33 + (c >> 5) + bl];
        }

        __syncthreads();   // staging tile reused by the second pass
    }
}

extern "C" void kernel_launch(void* const* d_in, const int* in_sizes, int n_in,
                              void* d_out, int out_size)
{
    const float* params       = (const float*)d_in[0];
    const int*   neigh_pix    = (const int*)d_in[1];
    const float* neigh_weight = (const float*)d_in[2];
    float*       out          = (float*)d_out;

    dim3 block(32, 8);
    dim3 grid(BATCH / BBLK);   // 15,625
    heal_encoding_kernel<<<grid, block>>>(params, neigh_pix, neigh_weight, out);
}

// round 11
// speedup vs baseline: 1.2405x; 1.2405x over previous
#include <cuda_runtime.h>
#include <cstddef>

// HealEncoding: out[b, f*NLVL + l] = sum_{n<4} params[l, neigh_pix[l,n,b], f] * neigh_weight[l,n,b]
// params: (8,196608,8) f32; neigh_pix: (8,4,1M) i32; neigh_weight: (8,4,1M) f32; out: (1M,64) f32

#define NLVL  8
#define NPIX  196608
#define BATCH 1000000
#define BBLK  32          // batch elements per block (2 per thread)

// Block (32,8): warp == one level. Pair-cooperative gather (lanes 2j,2j+1 split
// the 32B feature row; h = lane&1 -> 16B half): 1 l1tex wavefront per random
// pixel — measured at the 1.0 wf/cyc hardware floor. vs R8 (137.8us): the lvl0
// warp keeps its whole 384B table in registers (lanes 0..23, one 3-wf load per
// block) and gathers via __shfl_sync — removes lvl0's 24 gather wavefronts per
// 32 elements from the binding l1tex pipe, paid in idle issue slots.
__global__ void __launch_bounds__(256, 8)
heal_encoding_kernel(const float* __restrict__ params,
                     const int*   __restrict__ neigh_pix,
                     const float* __restrict__ neigh_weight,
                     float*       __restrict__ out)
{
    __shared__ float s[64 * 33];   // staging; addr = c*33 + (c>>5) + j2, conflict-free

    const int lane = threadIdx.x;
    const int lvl  = threadIdx.y;          // warp == level
    const int j    = lane >> 1;            // pixel-slot within warp [0,16)
    const int h    = lane & 1;             // 16B half of the 32B feature row
    const int b0   = blockIdx.x * BBLK;    // even

    const float4* __restrict__ p4 =
        reinterpret_cast<const float4*>(params) + lvl * (NPIX * 2);

    // lvl0 warp: whole table (12 pix * 2 float4 = 24 float4) in registers.
    const bool use_shfl = (lvl == 0);
    float4 tab = make_float4(0.f, 0.f, 0.f, 0.f);
    if (use_shfl && lane < 24) tab = __ldg(&p4[lane]);

    // Vectorized idx/weight loads: int2/float2 covering elements (2j, 2j+1).
    int2   pix2[4];
    float2 w2[4];
#pragma unroll
    for (int n = 0; n < 4; n++) {
        const int off = (lvl * 4 + n) * BATCH + b0;   // fits int32
        pix2[n] = __ldg(reinterpret_cast<const int2*>(neigh_pix + off) + j);
        w2[n]   = __ldg(reinterpret_cast<const float2*>(neigh_weight + off) + j);
    }

#pragma unroll
    for (int s2 = 0; s2 < 2; s2++) {
        float4 a = make_float4(0.f, 0.f, 0.f, 0.f);

#pragma unroll
        for (int np = 0; np < 2; np++) {
            const int pa = (s2 == 0) ? pix2[2*np+0].x : pix2[2*np+0].y;
            const int pb = (s2 == 0) ? pix2[2*np+1].x : pix2[2*np+1].y;
            float4 g0, g1;
            if (use_shfl) {                     // warp-uniform branch
                const int sa = pa * 2 + h;      // source lane holding that float4
                const int sb = pb * 2 + h;
                g0.x = __shfl_sync(0xffffffffu, tab.x, sa);
                g0.y = __shfl_sync(0xffffffffu, tab.y, sa);
                g0.z = __shfl_sync(0xffffffffu, tab.z, sa);
                g0.w = __shfl_sync(0xffffffffu, tab.w, sa);
                g1.x = __shfl_sync(0xffffffffu, tab.x, sb);
                g1.y = __shfl_sync(0xffffffffu, tab.y, sb);
                g1.z = __shfl_sync(0xffffffffu, tab.z, sb);
                g1.w = __shfl_sync(0xffffffffu, tab.w, sb);
            } else {
                g0 = __ldg(&p4[pa * 2 + h]);
                g1 = __ldg(&p4[pb * 2 + h]);
            }
            const float wa = (s2 == 0) ? w2[2*np+0].x : w2[2*np+0].y;
            const float wb = (s2 == 0) ? w2[2*np+1].x : w2[2*np+1].y;
            a.x = fmaf(wa, g0.x, a.x);  a.x = fmaf(wb, g1.x, a.x);
            a.y = fmaf(wa, g0.y, a.y);  a.y = fmaf(wb, g1.y, a.y);
            a.z = fmaf(wa, g0.z, a.z);  a.z = fmaf(wb, g1.z, a.z);
            a.w = fmaf(wa, g0.w, a.w);  a.w = fmaf(wb, g1.w, a.w);
        }

        // Stage element j2 = 2j+s2; out column c = (4h+k)*8 + lvl.
        // addr = c*33 + (c>>5) + j2 -> bank = const + 2j + h = const + lane:
        // conflict-free.
        const int j2 = 2 * j + s2;
#pragma unroll
        for (int k = 0; k < 4; k++) {
            const int c = (h * 4 + k) * NLVL + lvl;
            const float v = (k == 0) ? a.x : (k == 1) ? a.y : (k == 2) ? a.z : a.w;
            s[c * 33 + (c >> 5) + j2] = v;
        }
    }

    __syncthreads();

    // Coalesced write-out: 32 b x 64 cols = 2048 floats, 8 iters.
    // Read bank = (c + bl + const) % 32 distinct across warp: conflict-free.
    const int tid = lvl * 32 + lane;
    float* __restrict__ outp = out + (size_t)b0 * 64;
#pragma unroll
    for (int i = 0; i < 8; i++) {
        const int e  = i * 256 + tid;
        const int bl = e >> 6;
        const int c  = e & 63;
        outp[e] = s[c * 33 + (c >> 5) + bl];
    }
}

extern "C" void kernel_launch(void* const* d_in, const int* in_sizes, int n_in,
                              void* d_out, int out_size)
{
    const float* params       = (const float*)d_in[0];
    const int*   neigh_pix    = (const int*)d_in[1];
    const float* neigh_weight = (const float*)d_in[2];
    float*       out          = (float*)d_out;

    dim3 block(32, 8);
    dim3 grid(BATCH / BBLK);   // 31,250
    heal_encoding_kernel<<<grid, block>>>(params, neigh_pix, neigh_weight, out);
}